// round 17
// baseline (speedup 1.0000x reference)
#include <cuda_runtime.h>
#include <cuda_bf16.h>
#include <math.h>

// Problem dims
#define TT 512
#define BB 64
#define II 512
#define HH 512

// Phase-2: 128 blocks = 8 groups (8 batches) x 16 j-tiles (32 j each).
#define NBLK 128
#define GRPS 8
#define GBLK 16
#define JT   32
#define BT   8
#define HSTR 520            // h_sh row stride in floats (512 + 8 pad)
#define RSTR 37             // reduction row stride in floats

__device__ __align__(16) float g_hbuf[2 * BB * HH];
__device__ __align__(16) unsigned g_arrive[NBLK];   // zero-init; monotonic

// ---- f32x2 helpers -------------------------------------------------------
__device__ __forceinline__ unsigned long long pack2(float x, float y) {
    unsigned long long r;
    asm("mov.b64 %0, {%1, %2};" : "=l"(r) : "f"(x), "f"(y));
    return r;
}
__device__ __forceinline__ float hadd2(unsigned long long v) {
    float lo, hi;
    asm("mov.b64 {%0, %1}, %2;" : "=f"(lo), "=f"(hi) : "l"(v));
    return lo + hi;
}
#define FMA2(c, a, b) \
    asm("fma.rn.f32x2 %0, %1, %2, %3;" : "=l"(c) : "l"(a), "l"(b), "l"(c))

__device__ __forceinline__ unsigned ld_acq_gpu(const unsigned* p) {
    unsigned v;
    asm volatile("ld.acquire.gpu.global.u32 %0, [%1];" : "=r"(v) : "l"(p));
    return v;
}
__device__ __forceinline__ void st_rel_gpu(unsigned* p, unsigned v) {
    asm volatile("st.release.gpu.global.u32 [%0], %1;" :: "l"(p), "r"(v)
                 : "memory");
}

// ---------------------------------------------------------------------------
// Phase 1: xp = X @ W^T  (exact R5 kernel, ~430us measured)
// ---------------------------------------------------------------------------
__global__ void __launch_bounds__(256) gemm_xp_kernel(
    const float* __restrict__ X, const float* __restrict__ W,
    float* __restrict__ C)
{
    const int K = II, N = HH;
    __shared__ __align__(16) float As[16][128];
    __shared__ __align__(16) float Bs[16][128];

    const int bm = blockIdx.x * 128;
    const int bn = blockIdx.y * 128;
    const int tid = threadIdx.x;
    const int tx = tid & 15;
    const int ty = tid >> 4;

    float acc[8][8];
#pragma unroll
    for (int i = 0; i < 8; i++)
#pragma unroll
        for (int j = 0; j < 8; j++) acc[i][j] = 0.0f;

    for (int k0 = 0; k0 < K; k0 += 16) {
#pragma unroll
        for (int l = 0; l < 2; l++) {
            int idx = tid + l * 256;
            int r = idx >> 2;
            int c = (idx & 3) * 4;
            float4 va = *(const float4*)&X[(size_t)(bm + r) * K + k0 + c];
            As[c + 0][r] = va.x; As[c + 1][r] = va.y;
            As[c + 2][r] = va.z; As[c + 3][r] = va.w;
            float4 vb = *(const float4*)&W[(size_t)(bn + r) * K + k0 + c];
            Bs[c + 0][r] = vb.x; Bs[c + 1][r] = vb.y;
            Bs[c + 2][r] = vb.z; Bs[c + 3][r] = vb.w;
        }
        __syncthreads();

#pragma unroll
        for (int kk = 0; kk < 16; kk++) {
            float a[8], b[8];
            *(float4*)&a[0] = *(const float4*)&As[kk][ty * 8];
            *(float4*)&a[4] = *(const float4*)&As[kk][ty * 8 + 4];
            *(float4*)&b[0] = *(const float4*)&Bs[kk][tx * 8];
            *(float4*)&b[4] = *(const float4*)&Bs[kk][tx * 8 + 4];
#pragma unroll
            for (int i = 0; i < 8; i++)
#pragma unroll
                for (int j = 0; j < 8; j++)
                    acc[i][j] = fmaf(a[i], b[j], acc[i][j]);
        }
        __syncthreads();
    }

#pragma unroll
    for (int i = 0; i < 8; i++) {
        int row = bm + ty * 8 + i;
        float4 v0 = make_float4(acc[i][0], acc[i][1], acc[i][2], acc[i][3]);
        float4 v1 = make_float4(acc[i][4], acc[i][5], acc[i][6], acc[i][7]);
        *(float4*)&C[(size_t)row * N + bn + tx * 8]     = v0;
        *(float4*)&C[(size_t)row * N + bn + tx * 8 + 4] = v1;
    }
}

// ---------------------------------------------------------------------------
// Phase 2: persistent recurrence — R16 engine with DISTRIBUTED poll+stage:
//   each thread's staged k4 = tid&127 maps to exactly one producer block
//   (jt_src = k4>>3), so it acquire-polls only that flag, then immediately
//   stages its 4 float4s. Early producers' chunks stage while late flags
//   are still in flight; one barrier (pre-compute) replaces two.
// ---------------------------------------------------------------------------
__global__ void __launch_bounds__(256) rnn_recurrence_kernel(
    const float* __restrict__ w_hh, float* __restrict__ out, int has_last)
{
    extern __shared__ __align__(16) float smem[];
    float* h_sh = smem;                       // [BT][HSTR] = 8 x 520
    float* red  = smem + BT * HSTR;           // [256][RSTR] = 256 x 37

    const int tid = threadIdx.x;
    const int bid = blockIdx.x;
    const int grp = bid >> 4;
    const int jt  = bid & 15;
    const int b0  = grp * BT;
    const int j0  = jt * JT;

    const int ks = tid >> 3;       // 0..31
    const int jp = tid & 7;        // 0..7
    const int kbase = ks * 16;
    const int cxor = (ks & 2) << 1;

    // staging identity: one k4 slot, one producer flag
    const int sk4  = tid & 127;                       // staged k4
    const int sb0  = tid >> 7;                        // base b (0/1)
    const int soff = (sk4 * 4) ^ (((sk4 >> 3) & 1) << 2);
    const unsigned* myflag = &g_arrive[grp * GBLK + (sk4 >> 3)];

    __shared__ unsigned s_base;
    if (tid == 0) s_base = *((volatile unsigned*)&g_arrive[bid]);

    // ---- W slab in registers (compile-time indices only!)
    unsigned long long wreg[4][8];
#pragma unroll
    for (int jj = 0; jj < 4; jj++) {
        const float* wr = &w_hh[(size_t)(j0 + jp * 4 + jj) * HH + kbase];
#pragma unroll
        for (int q = 0; q < 4; q++) {
            float4 v = *(const float4*)&wr[q * 4];
            wreg[jj][q * 2 + 0] = pack2(v.x, v.y);
            wreg[jj][q * 2 + 1] = pack2(v.z, v.w);
        }
    }
    __syncthreads();
    const unsigned base = s_base;

    const int gj = j0 + (tid & 31);
    const int gb = b0 + (tid >> 5);

    float* __restrict__ hall  = out;
    float* __restrict__ hlast = out + (size_t)TT * BB * HH;

    for (int t = 0; t < TT; t++) {
        float xp = hall[((size_t)t * BB + gb) * HH + gj];   // prefetch

        float hsum = 0.0f;
        if (t > 0) {
            // ---- distributed poll + stage: wait ONLY for own producer,
            //      then stage own 4 float4s (overlaps with late peers)
            {
                const unsigned tgt = base + (unsigned)t;
                while (ld_acq_gpu(myflag) < tgt) __nanosleep(32);

                const int prev = (t - 1) & 1;
                const float4* src = (const float4*)&g_hbuf[
                    (size_t)prev * BB * HH + (size_t)b0 * HH];
                float4 v0 = __ldcg(&src[(size_t)(sb0 + 0) * 128 + sk4]);
                float4 v1 = __ldcg(&src[(size_t)(sb0 + 2) * 128 + sk4]);
                float4 v2 = __ldcg(&src[(size_t)(sb0 + 4) * 128 + sk4]);
                float4 v3 = __ldcg(&src[(size_t)(sb0 + 6) * 128 + sk4]);
                *(float4*)&h_sh[(sb0 + 0) * HSTR + soff] = v0;
                *(float4*)&h_sh[(sb0 + 2) * HSTR + soff] = v1;
                *(float4*)&h_sh[(sb0 + 4) * HSTR + soff] = v2;
                *(float4*)&h_sh[(sb0 + 6) * HSTR + soff] = v3;
            }
            __syncthreads();   // all staged data visible

            // ---- compute: acc[jj][bb] over 16 k (f32x2 pairs)
            unsigned long long acc[4][8];
#pragma unroll
            for (int jj = 0; jj < 4; jj++)
#pragma unroll
                for (int bb = 0; bb < 8; bb++) acc[jj][bb] = 0ULL;

#pragma unroll
            for (int q = 0; q < 4; q++) {
                const int koff = kbase + ((q * 4) ^ cxor);
#pragma unroll
                for (int bb = 0; bb < 8; bb++) {
                    ulonglong2 hv = *(const ulonglong2*)&h_sh[
                        bb * HSTR + koff];
#pragma unroll
                    for (int jj = 0; jj < 4; jj++) {
                        FMA2(acc[jj][bb], wreg[jj][q * 2 + 0], hv.x);
                        FMA2(acc[jj][bb], wreg[jj][q * 2 + 1], hv.y);
                    }
                }
            }

            // ---- partials -> red[row][ks], row = bb*32 + jp*4 + jj
#pragma unroll
            for (int jj = 0; jj < 4; jj++)
#pragma unroll
                for (int bb = 0; bb < 8; bb++)
                    red[(bb * 32 + jp * 4 + jj) * RSTR + ks] =
                        hadd2(acc[jj][bb]);
            __syncthreads();

            const float* rr = &red[tid * RSTR];
            float s = 0.0f;
#pragma unroll
            for (int i = 0; i < 32; i++) s += rr[i];
            hsum = s;
        }

        float h = tanhf(xp + hsum);

        // state store first, then signal (hall store off critical path)
        g_hbuf[((size_t)(t & 1) * BB + gb) * HH + gj] = h;

        if (t != TT - 1) {
            __syncthreads();               // fence.cta: all hbuf stores ordered
            if (tid == 0)
                st_rel_gpu(&g_arrive[bid], base + 1u + (unsigned)t);
        }

        hall[((size_t)t * BB + gb) * HH + gj] = h;
        if (has_last && t == TT - 1)
            hlast[(size_t)gb * HH + gj] = h;
    }
}

// ---------------------------------------------------------------------------
extern "C" void kernel_launch(void* const* d_in, const int* in_sizes, int n_in,
                              void* d_out, int out_size) {
    const float* x    = (const float*)d_in[0];   // (T, B, I)
    const float* w_ih = (const float*)d_in[1];   // (H, I)
    const float* w_hh = (const float*)d_in[2];   // (H, H)
    float* out = (float*)d_out;

    dim3 g1((TT * BB) / 128, HH / 128);
    gemm_xp_kernel<<<g1, 256>>>(x, w_ih, out);

    int smem_bytes = (BT * HSTR + 256 * RSTR) * (int)sizeof(float); // ~54KB
    cudaFuncSetAttribute(rnn_recurrence_kernel,
                         cudaFuncAttributeMaxDynamicSharedMemorySize, smem_bytes);
    int has_last = (out_size >= TT * BB * HH + BB * HH) ? 1 : 0;
    rnn_recurrence_kernel<<<NBLK, 256, smem_bytes>>>(w_hh, out, has_last);
}